// round 15
// baseline (speedup 1.0000x reference)
#include <cuda_runtime.h>
#include <cuda_bf16.h>
#include <cstdint>

#define C_CLASSES 50000
#define C_PAD     50176            // 392 * 128 = 1568 * 32
#define B_N       512
#define D_DIM     128
#define K2F       46.166241308446828f   // 32 * log2(e)
#define MRGF      0.1f

// ---------------- device scratch (static, no runtime alloc) ----------------
__device__ __align__(16) float          g_Xn[B_N * D_DIM];
__device__ __align__(16) __nv_bfloat16  g_Xn_bf[B_N * D_DIM];
__device__ __align__(16) __nv_bfloat16  g_Pn_bf[C_PAD * D_DIM];   // ~12.8 MB
__device__ float g_center_sim[C_CLASSES];
__device__ float g_cterm[C_PAD];     // K2 * (mrg + adj), log2 units
__device__ float g_Nbuf[C_PAD];      // UNSCALED: sum_b exp2(K2*cos) minus one-hot
__device__ float g_Pbuf[C_CLASSES];  // UNSCALED: sum onehot exp2(-K2*cos)
__device__ float g_acc[4];           // [0]=posAcc, [1]=negAcc, [2]=absAcc
__device__ int   g_num_valid;
__device__ int   g_done;
__device__ int   g_ph1;
// slot-based per-class stats scratch (slot = first batch index of the class)
__device__ int   g_first[C_CLASSES];
__device__ float g_ssum[B_N * D_DIM];
__device__ float g_ssq [B_N * D_DIM];
__device__ int   g_scnt[B_N];

__device__ __forceinline__ float ex2f(float x) {
    float y;
    asm("ex2.approx.ftz.f32 %0, %1;" : "=f"(y) : "f"(x));
    return y;
}

__device__ __forceinline__ float wred(float v) {
#pragma unroll
    for (int o = 16; o; o >>= 1) v += __shfl_xor_sync(0xffffffffu, v, o);
    return v;
}

template<int N>
__device__ __forceinline__ void wredN(float* v) {
#pragma unroll
    for (int o = 16; o; o >>= 1)
#pragma unroll
        for (int i = 0; i < N; i++)
            v[i] += __shfl_xor_sync(0xffffffffu, v[i], o);
}

__device__ __forceinline__ unsigned smem_u32(const void* p) {
    unsigned a;
    asm("{ .reg .u64 t; cvta.to.shared.u64 t, %1; cvt.u32.u64 %0, t; }"
        : "=r"(a) : "l"(p));
    return a;
}

// ---------------- kernel Z: zero all accumulators + scratch (fused) --------
__global__ void k_zero(const int* __restrict__ T) {
    int i = blockIdx.x * 256 + threadIdx.x;   // 256 blocks -> 65536 threads
    if (i < B_N * D_DIM) { g_ssum[i] = 0.f; g_ssq[i] = 0.f; }
    if (i < C_PAD)     g_Nbuf[i] = 0.f;
    if (i < C_CLASSES) g_Pbuf[i] = 0.f;
    if (i < B_N) {
        g_scnt[i] = 0;
        g_first[T[i]] = 0x7fffffff;   // init only touched classes
    }
    if (i < 4)  g_acc[i] = 0.f;
    if (i == 0) { g_num_valid = 0; g_done = 0; g_ph1 = 0; }
}

// ---------------- kernel X: normalize X + first-occurrence map -------------
__global__ void k_xnorm(const float* __restrict__ X, const int* __restrict__ T) {
    int row = blockIdx.x, d = threadIdx.x;     // 512 blocks x 128 threads
    __shared__ float sp[4];
    float x = X[row * D_DIM + d];
    float v = wred(x * x);
    if ((d & 31) == 0) sp[d >> 5] = v;
    __syncthreads();
    float ss = sp[0] + sp[1] + sp[2] + sp[3] + 1e-12f;
    float y = x * rsqrtf(ss);
    g_Xn[row * D_DIM + d]    = y;
    g_Xn_bf[row * D_DIM + d] = __float2bfloat16(y);
    if (d == 0) atomicMin(&g_first[T[row]], row);
}

// ---------------- kernel P: normalize proxies + center stats + class acc ---
// 4 rows per warp, 8 LDG.128 up-front (MLP=8), interleaved shfl chains.
// |c| reduced once per warp (combined over 4 rows) instead of per-row.
__global__ __launch_bounds__(256) void k_pnorm(const float* __restrict__ proxies,
                                               const float* __restrict__ centers,
                                               const int*   __restrict__ T) {
    const int warp = threadIdx.x >> 5, lane = threadIdx.x & 31;
    const int r0 = (blockIdx.x * 8 + warp) * 4;       // 1568 blocks cover C_PAD
    __shared__ float s_ab;
    if (threadIdx.x == 0) s_ab = 0.f;
    __syncthreads();

    const float4 z4 = make_float4(0.f, 0.f, 0.f, 0.f);
    float4 p[4], c4[4];
#pragma unroll
    for (int i = 0; i < 4; i++) {
        int r = r0 + i;
        p[i]  = (r < C_CLASSES)
              ? reinterpret_cast<const float4*>(proxies + (size_t)r * D_DIM)[lane] : z4;
    }
#pragma unroll
    for (int i = 0; i < 4; i++) {
        int r = r0 + i;
        c4[i] = (r < C_CLASSES)
              ? reinterpret_cast<const float4*>(centers + (size_t)r * D_DIM)[lane] : z4;
    }

    float ss[4];
#pragma unroll
    for (int i = 0; i < 4; i++)
        ss[i] = p[i].x * p[i].x + p[i].y * p[i].y + p[i].z * p[i].z + p[i].w * p[i].w;
    wredN<4>(ss);

    float inv[4];
#pragma unroll
    for (int i = 0; i < 4; i++) inv[i] = rsqrtf(ss[i] + 1e-12f);

    // store normalized bf16 rows (pad rows have p=0 -> store zeros)
#pragma unroll
    for (int i = 0; i < 4; i++) {
        __nv_bfloat162 w0 = __floats2bfloat162_rn(p[i].x * inv[i], p[i].y * inv[i]);
        __nv_bfloat162 w1 = __floats2bfloat162_rn(p[i].z * inv[i], p[i].w * inv[i]);
        uint2 pk = make_uint2(*reinterpret_cast<unsigned*>(&w0),
                              *reinterpret_cast<unsigned*>(&w1));
        reinterpret_cast<uint2*>(g_Pn_bf + (size_t)(r0 + i) * D_DIM)[lane] = pk;
    }

    // 8 interleaved per-row reductions (dot, c.c) + 1 combined |c| reduction
    float dca[8];
    float abt = 0.f;
#pragma unroll
    for (int i = 0; i < 4; i++) {
        dca[i]     = inv[i] * (p[i].x * c4[i].x + p[i].y * c4[i].y +
                               p[i].z * c4[i].z + p[i].w * c4[i].w);
        dca[4 + i] = c4[i].x * c4[i].x + c4[i].y * c4[i].y +
                     c4[i].z * c4[i].z + c4[i].w * c4[i].w;
        abt += fabsf(c4[i].x) + fabsf(c4[i].y) + fabsf(c4[i].z) + fabsf(c4[i].w);
    }
    wredN<8>(dca);
    abt = wred(abt);     // pad rows contribute 0

    if (lane == 0) {
#pragma unroll
        for (int i = 0; i < 4; i++) {
            int r = r0 + i;
            if (r < C_CLASSES) {
                float pn2   = ss[i] * inv[i] * inv[i];
                float pnorm = fmaxf(sqrtf(pn2), 1e-8f);
                float cnorm = fmaxf(sqrtf(dca[4 + i]), 1e-8f);
                g_center_sim[r] = dca[i] / (pnorm * cnorm);
            }
            g_cterm[r] = K2F * MRGF;                 // default: adj = 0
        }
        atomicAdd(&s_ab, abt);
    }
    __syncthreads();
    if (threadIdx.x == 0) atomicAdd(&g_acc[2], s_ab);

    // embedded per-class accumulation: blocks 0..511 map to batch rows,
    // threads 0..127 map to dims (g_first/g_Xn final after k_xnorm)
    if (blockIdx.x < B_N && threadIdx.x < D_DIM) {
        int b = blockIdx.x, d = threadIdx.x;
        int slot = g_first[T[b]];
        float x = g_Xn[b * D_DIM + d];
        atomicAdd(&g_ssum[slot * D_DIM + d], x);
        atomicAdd(&g_ssq [slot * D_DIM + d], x * x);
        if (d == 0) atomicAdd(&g_scnt[slot], 1);
    }
}

// ---------------- kernel G: mma.sync bf16 GEMM fused with exp2-sum ---------
// PROFILED SLOT (#4). R14 config UNCHANGED (near the legacy-HMMA rate floor:
// ~16 cyc/HMMA.16816/SMSP, pipe ~90% saturated). Merged halves, grid 392,
// 8 warps x 16 classes, 3 CTAs/SM, B fragments + ns register-resident.
__global__ __launch_bounds__(256, 3) void k_gemm() {
    extern __shared__ __align__(16) unsigned char smraw[];
    __nv_bfloat16* sA = reinterpret_cast<__nv_bfloat16*>(smraw);  // [256][136]
    const int tid = threadIdx.x, wid = tid >> 5, lane = tid & 31;
    const int tile = blockIdx.x;                 // 0..391
    const int cbase = tile * 128 + wid * 16;

    const int tg = lane & 3, g = lane >> 2;

    // B fragments: 16 classes x full K=128, register resident (32 regs)
    unsigned br[2][8][2];
#pragma unroll
    for (int t = 0; t < 2; t++) {
        const __nv_bfloat16* rowp = g_Pn_bf + (size_t)(cbase + t * 8 + g) * D_DIM;
#pragma unroll
        for (int ks = 0; ks < 8; ks++) {
            br[t][ks][0] = *reinterpret_cast<const unsigned*>(rowp + ks * 16 + tg * 2);
            br[t][ks][1] = *reinterpret_cast<const unsigned*>(rowp + ks * 16 + 8 + tg * 2);
        }
    }
    float ns[2][2] = {};

    const unsigned sbase = smem_u32(sA);
    const int sub = lane >> 3, rl = lane & 7;
    const int row_off = rl + ((sub & 1) << 3);
    const int k_off   = (sub >> 1) << 3;

    for (int half = 0; half < 2; half++) {
        // stage A half (256 x 128 bf16) with padded stride (272B rows)
        __syncthreads();                         // prior half's reads done
        for (int i = tid; i < 256 * 16; i += 256) {
            int r = i >> 4, q = i & 15;
            uint4 v = *reinterpret_cast<const uint4*>(
                g_Xn_bf + (half * 256 + r) * D_DIM + q * 8);
            *reinterpret_cast<uint4*>(sA + r * 136 + q * 8) = v;
        }
        __syncthreads();

        unsigned maddr = sbase + (unsigned)((row_off * 136 + k_off) * 2);
        for (int m = 0; m < 16; m++) {
            float acc[2][4] = {};
            unsigned a[2][4];
            asm volatile("ldmatrix.sync.aligned.m8n8.x4.shared.b16 {%0,%1,%2,%3}, [%4];"
                         : "=r"(a[0][0]), "=r"(a[0][1]), "=r"(a[0][2]), "=r"(a[0][3])
                         : "r"(maddr));
#pragma unroll
            for (int ks = 0; ks < 8; ks++) {
                if (ks < 7) {
                    unsigned* an = a[(ks + 1) & 1];
                    asm volatile("ldmatrix.sync.aligned.m8n8.x4.shared.b16 {%0,%1,%2,%3}, [%4];"
                                 : "=r"(an[0]), "=r"(an[1]), "=r"(an[2]), "=r"(an[3])
                                 : "r"(maddr + (unsigned)((ks + 1) * 32)));
                }
                const unsigned* ac = a[ks & 1];
#pragma unroll
                for (int t = 0; t < 2; t++) {
                    asm("mma.sync.aligned.m16n8k16.row.col.f32.bf16.bf16.f32 "
                        "{%0,%1,%2,%3}, {%4,%5,%6,%7}, {%8,%9}, {%0,%1,%2,%3};"
                        : "+f"(acc[t][0]), "+f"(acc[t][1]), "+f"(acc[t][2]), "+f"(acc[t][3])
                        : "r"(ac[0]), "r"(ac[1]), "r"(ac[2]), "r"(ac[3]),
                          "r"(br[t][ks][0]), "r"(br[t][ks][1]));
                }
            }
            maddr += 16 * 272;
#pragma unroll
            for (int t = 0; t < 2; t++) {
                ns[t][0] += ex2f(acc[t][0] * K2F) + ex2f(acc[t][2] * K2F);
                ns[t][1] += ex2f(acc[t][1] * K2F) + ex2f(acc[t][3] * K2F);
            }
        }
    }
    // reduce over the 8 row-groups (lanes xor 4,8,16)
#pragma unroll
    for (int o = 4; o < 32; o <<= 1)
#pragma unroll
        for (int t = 0; t < 2; t++)
#pragma unroll
            for (int j = 0; j < 2; j++)
                ns[t][j] += __shfl_xor_sync(0xffffffffu, ns[t][j], o);

    if (g == 0) {
#pragma unroll
        for (int t = 0; t < 2; t++)
#pragma unroll
            for (int j = 0; j < 2; j++)
                atomicAdd(&g_Nbuf[cbase + t * 8 + tg * 2 + j], ns[t][j]);
    }
}

// ---------------- kernel R: statfin phase + spin barrier + reduce + final --
// 256 blocks x 256 threads, all resident (spin barrier is deadlock-free).
// Phase 1: one-hot exp terms + per-class stats -> cterm (2 batch rows/block).
// Phase 2: apply cterm scales, log1p sums, final combine.
__global__ void k_reducefinal(const int* __restrict__ T,
                              const float* __restrict__ proxies,
                              float* __restrict__ out) {
    __shared__ float s1[2][4], s2[2][4], red[2][4];
    const int tid = threadIdx.x;
    const int hb = tid >> 7, d = tid & 127;      // half-block, dim
    const int b = blockIdx.x * 2 + hb;           // 512 batch rows
    const int c = T[b];

    // ---- phase 1a: one-hot cos (fp32 exact) ----
    const float* pr = proxies + (size_t)c * D_DIM;
    float p = pr[d];
    float v = wred(p * p);
    if ((d & 31) == 0) s1[hb][d >> 5] = v;
    __syncthreads();
    float ssq = s1[hb][0] + s1[hb][1] + s1[hb][2] + s1[hb][3];
    float inv = 1.0f / sqrtf(ssq + 1e-12f);
    float x = g_Xn[b * D_DIM + d];
    float v2 = wred(x * (p * inv));
    if ((d & 31) == 0) s2[hb][d >> 5] = v2;
    __syncthreads();
    if (d == 0) {
        float cosv = s2[hb][0] + s2[hb][1] + s2[hb][2] + s2[hb][3];
        atomicAdd(&g_Nbuf[c], -ex2f(K2F * cosv));   // remove one-hot from neg
        atomicAdd(&g_Pbuf[c],  ex2f(-K2F * cosv));  // unscaled pos term
    }

    // ---- phase 1b: per-class stats -> cterm (representative row only) ----
    bool rep = (g_first[c] == b);                // uniform per half-block
    float n   = (float)g_scnt[b];                // 0 for non-rep (result unused)
    float s   = g_ssum[b * D_DIM + d];
    float s2v = g_ssq [b * D_DIM + d];
    float mean = s / n;
    float var  = s2v / n - mean * mean;
    var = fminf(fmaxf(var, 1e-6f), 10.0f);
    float vv = wred(var);
    if ((d & 31) == 0) red[hb][d >> 5] = vv;
    __syncthreads();
    if (rep && d == 0) {
        float vmean = (red[hb][0] + red[hb][1] + red[hb][2] + red[hb][3]) * (1.0f / 128.0f);
        float vw  = 1.0f / (1.0f + vmean);
        float adj = g_center_sim[c] * vw * 0.15f;
        g_cterm[c] = K2F * (MRGF + adj);
        atomicAdd(&g_num_valid, 1);
    }

    // ---- spin barrier across all 256 blocks (all resident) ----
    __syncthreads();
    if (tid == 0) {
        __threadfence();
        atomicAdd(&g_ph1, 1);
        while (*(volatile int*)&g_ph1 < 256) { }
    }
    __syncthreads();
    __threadfence();

    // ---- phase 2: scaled log1p sums ----
    int i = blockIdx.x * 256 + tid;              // covers 65536 >= C_CLASSES
    float nl = 0.f, pl = 0.f;
    if (i < C_CLASSES) {
        float ctm = g_cterm[i];
        nl = log1pf(fmaxf(ex2f(ctm) * g_Nbuf[i], 0.f));
        pl = log1pf(ex2f(2.0f * K2F * MRGF - ctm) * g_Pbuf[i]);
    }
    __shared__ float sn[8], sp2[8];
    float a  = wred(nl);
    float b2 = wred(pl);
    int w = tid >> 5, l = tid & 31;
    if (l == 0) { sn[w] = a; sp2[w] = b2; }
    __syncthreads();
    if (tid == 0) {
        float tn = 0.f, tp = 0.f;
#pragma unroll
        for (int k = 0; k < 8; k++) { tn += sn[k]; tp += sp2[k]; }
        atomicAdd(&g_acc[1], tn);
        atomicAdd(&g_acc[0], tp);
        __threadfence();
        int prev = atomicAdd(&g_done, 1);
        if (prev == 255) {
            volatile float* ac = g_acc;
            float pos = ac[0] / (float)g_num_valid;
            float neg = ac[1] * (1.0f / 50000.0f);
            float reg = ac[2] * (1.0f / (50000.0f * 128.0f));
            out[0] = pos + neg + 0.01f * reg;
        }
    }
}

// ---------------- launch ----------------------------------------------------
// 5 launches; k_gemm stays at app-launch #4 (the ncu -s 5 -c 1 window).
extern "C" void kernel_launch(void* const* d_in, const int* in_sizes, int n_in,
                              void* d_out, int out_size) {
    const float* X       = (const float*)d_in[0];
    const int*   T       = (const int*)d_in[1];
    const float* proxies = (const float*)d_in[2];
    const float* centers = (const float*)d_in[3];
    float* out = (float*)d_out;

    const int gemm_smem = 256 * 136 * 2;   // 69632 B dynamic smem
    cudaFuncSetAttribute(k_gemm, cudaFuncAttributeMaxDynamicSharedMemorySize, gemm_smem);

    k_zero       <<<256, 256>>>(T);
    k_xnorm      <<<512, 128>>>(X, T);
    k_pnorm      <<<C_PAD / 32, 256>>>(proxies, centers, T);
    k_gemm       <<<392, 256, gemm_smem>>>();
    k_reducefinal<<<256, 256>>>(T, proxies, out);
}

// round 16
// speedup vs baseline: 1.0513x; 1.0513x over previous
#include <cuda_runtime.h>
#include <cuda_bf16.h>
#include <cstdint>

#define C_CLASSES 50000
#define C_PAD     50176            // 392 * 128 = 1568 * 32
#define B_N       512
#define D_DIM     128
#define K2F       46.166241308446828f   // 32 * log2(e)
#define MRGF      0.1f

// ---------------- device scratch (static, no runtime alloc) ----------------
__device__ __align__(16) float          g_Xn[B_N * D_DIM];
__device__ __align__(16) __nv_bfloat16  g_Xn_bf[B_N * D_DIM];
__device__ __align__(16) __nv_bfloat16  g_Pn_bf[C_PAD * D_DIM];   // ~12.8 MB
__device__ float g_center_sim[C_CLASSES];
__device__ float g_cterm[C_PAD];     // K2 * (mrg + adj), log2 units
__device__ float g_Nbuf[C_PAD];      // UNSCALED: sum_b exp2(K2*cos) minus one-hot
__device__ float g_Pbuf[C_CLASSES];  // UNSCALED: sum onehot exp2(-K2*cos)
__device__ float g_acc[4];           // [0]=posAcc, [1]=negAcc, [2]=absAcc
__device__ int   g_num_valid;
__device__ int   g_done;
__device__ int   g_ph1;
__device__ int   g_ph2;
// g_first: 0 = untouched (zero-init at module load, SELF-CLEANED each run);
// touched classes hold B_N - min_row (set via atomicMax).
__device__ int   g_first[C_CLASSES];
__device__ float g_ssum[B_N * D_DIM];
__device__ float g_ssq [B_N * D_DIM];
__device__ int   g_scnt[B_N];

__device__ __forceinline__ float ex2f(float x) {
    float y;
    asm("ex2.approx.ftz.f32 %0, %1;" : "=f"(y) : "f"(x));
    return y;
}

__device__ __forceinline__ float wred(float v) {
#pragma unroll
    for (int o = 16; o; o >>= 1) v += __shfl_xor_sync(0xffffffffu, v, o);
    return v;
}

template<int N>
__device__ __forceinline__ void wredN(float* v) {
#pragma unroll
    for (int o = 16; o; o >>= 1)
#pragma unroll
        for (int i = 0; i < N; i++)
            v[i] += __shfl_xor_sync(0xffffffffu, v[i], o);
}

__device__ __forceinline__ unsigned smem_u32(const void* p) {
    unsigned a;
    asm("{ .reg .u64 t; cvta.to.shared.u64 t, %1; cvt.u32.u64 %0, t; }"
        : "=r"(a) : "l"(p));
    return a;
}

// ---------------- kernel XZ: zero scratch + normalize X + first-map --------
// 512 blocks x 128 threads = 65536 threads: zeroing grid == xnorm grid.
__global__ void k_xnz(const float* __restrict__ X, const int* __restrict__ T) {
    int row = blockIdx.x, d = threadIdx.x;
    int i = row * D_DIM + d;
    // zero per-run scratch (g_first NOT zeroed: self-cleaned, 0 sentinel)
    g_ssum[i] = 0.f; g_ssq[i] = 0.f;
    if (i < C_PAD)     g_Nbuf[i] = 0.f;
    if (i < C_CLASSES) g_Pbuf[i] = 0.f;
    if (i < B_N)       g_scnt[i] = 0;
    if (i < 4)         g_acc[i] = 0.f;
    if (i == 0) { g_num_valid = 0; g_done = 0; g_ph1 = 0; g_ph2 = 0; }

    __shared__ float sp[4];
    float x = X[i];
    float v = wred(x * x);
    if ((d & 31) == 0) sp[d >> 5] = v;
    __syncthreads();
    float ss = sp[0] + sp[1] + sp[2] + sp[3] + 1e-12f;
    float y = x * rsqrtf(ss);
    g_Xn[i]    = y;
    g_Xn_bf[i] = __float2bfloat16(y);
    // representative = min row  ->  atomicMax of (B_N - row), 0 = untouched
    if (d == 0) atomicMax(&g_first[T[row]], B_N - row);
}

// ---------------- kernel P: normalize proxies + center stats + class acc ---
__global__ __launch_bounds__(256) void k_pnorm(const float* __restrict__ proxies,
                                               const float* __restrict__ centers,
                                               const int*   __restrict__ T) {
    const int warp = threadIdx.x >> 5, lane = threadIdx.x & 31;
    const int r0 = (blockIdx.x * 8 + warp) * 4;       // 1568 blocks cover C_PAD
    __shared__ float s_ab;
    if (threadIdx.x == 0) s_ab = 0.f;
    __syncthreads();

    const float4 z4 = make_float4(0.f, 0.f, 0.f, 0.f);
    float4 p[4], c4[4];
#pragma unroll
    for (int i = 0; i < 4; i++) {
        int r = r0 + i;
        p[i]  = (r < C_CLASSES)
              ? reinterpret_cast<const float4*>(proxies + (size_t)r * D_DIM)[lane] : z4;
    }
#pragma unroll
    for (int i = 0; i < 4; i++) {
        int r = r0 + i;
        c4[i] = (r < C_CLASSES)
              ? reinterpret_cast<const float4*>(centers + (size_t)r * D_DIM)[lane] : z4;
    }

    float ss[4];
#pragma unroll
    for (int i = 0; i < 4; i++)
        ss[i] = p[i].x * p[i].x + p[i].y * p[i].y + p[i].z * p[i].z + p[i].w * p[i].w;
    wredN<4>(ss);

    float inv[4];
#pragma unroll
    for (int i = 0; i < 4; i++) inv[i] = rsqrtf(ss[i] + 1e-12f);

#pragma unroll
    for (int i = 0; i < 4; i++) {
        __nv_bfloat162 w0 = __floats2bfloat162_rn(p[i].x * inv[i], p[i].y * inv[i]);
        __nv_bfloat162 w1 = __floats2bfloat162_rn(p[i].z * inv[i], p[i].w * inv[i]);
        uint2 pk = make_uint2(*reinterpret_cast<unsigned*>(&w0),
                              *reinterpret_cast<unsigned*>(&w1));
        reinterpret_cast<uint2*>(g_Pn_bf + (size_t)(r0 + i) * D_DIM)[lane] = pk;
    }

    float dca[8];
    float abt = 0.f;
#pragma unroll
    for (int i = 0; i < 4; i++) {
        dca[i]     = inv[i] * (p[i].x * c4[i].x + p[i].y * c4[i].y +
                               p[i].z * c4[i].z + p[i].w * c4[i].w);
        dca[4 + i] = c4[i].x * c4[i].x + c4[i].y * c4[i].y +
                     c4[i].z * c4[i].z + c4[i].w * c4[i].w;
        abt += fabsf(c4[i].x) + fabsf(c4[i].y) + fabsf(c4[i].z) + fabsf(c4[i].w);
    }
    wredN<8>(dca);
    abt = wred(abt);

    if (lane == 0) {
#pragma unroll
        for (int i = 0; i < 4; i++) {
            int r = r0 + i;
            if (r < C_CLASSES) {
                float pn2   = ss[i] * inv[i] * inv[i];
                float pnorm = fmaxf(sqrtf(pn2), 1e-8f);
                float cnorm = fmaxf(sqrtf(dca[4 + i]), 1e-8f);
                g_center_sim[r] = dca[i] / (pnorm * cnorm);
            }
            g_cterm[r] = K2F * MRGF;                 // default: adj = 0
        }
        atomicAdd(&s_ab, abt);
    }
    __syncthreads();
    if (threadIdx.x == 0) atomicAdd(&g_acc[2], s_ab);

    // embedded per-class accumulation (blocks 0..511 = batch rows)
    if (blockIdx.x < B_N && threadIdx.x < D_DIM) {
        int b = blockIdx.x, d = threadIdx.x;
        int slot = B_N - g_first[T[b]];
        float x = g_Xn[b * D_DIM + d];
        atomicAdd(&g_ssum[slot * D_DIM + d], x);
        atomicAdd(&g_ssq [slot * D_DIM + d], x * x);
        if (d == 0) atomicAdd(&g_scnt[slot], 1);
    }
}

// ---------------- kernel GF: GEMM + grid barrier + statfin + reduce + final
// Mainloop byte-identical to R14 best (legacy-HMMA rate floor, ~90% sat).
// All 392 blocks resident (launch_bounds(256,3): regs<=85, smem 209KB/SM).
__global__ __launch_bounds__(256, 3) void k_gemmfinal(const int* __restrict__ T,
                                                      const float* __restrict__ proxies,
                                                      float* __restrict__ out) {
    extern __shared__ __align__(16) unsigned char smraw[];
    __nv_bfloat16* sA = reinterpret_cast<__nv_bfloat16*>(smraw);  // [256][136]
    const int tid = threadIdx.x, wid = tid >> 5, lane = tid & 31;
    const int tile = blockIdx.x;                 // 0..391
    const int cbase = tile * 128 + wid * 16;

    const int tg = lane & 3, g = lane >> 2;

    unsigned br[2][8][2];
#pragma unroll
    for (int t = 0; t < 2; t++) {
        const __nv_bfloat16* rowp = g_Pn_bf + (size_t)(cbase + t * 8 + g) * D_DIM;
#pragma unroll
        for (int ks = 0; ks < 8; ks++) {
            br[t][ks][0] = *reinterpret_cast<const unsigned*>(rowp + ks * 16 + tg * 2);
            br[t][ks][1] = *reinterpret_cast<const unsigned*>(rowp + ks * 16 + 8 + tg * 2);
        }
    }
    float ns[2][2] = {};

    const unsigned sbase = smem_u32(sA);
    const int sub = lane >> 3, rl = lane & 7;
    const int row_off = rl + ((sub & 1) << 3);
    const int k_off   = (sub >> 1) << 3;

    for (int half = 0; half < 2; half++) {
        __syncthreads();
        for (int i = tid; i < 256 * 16; i += 256) {
            int r = i >> 4, q = i & 15;
            uint4 v = *reinterpret_cast<const uint4*>(
                g_Xn_bf + (half * 256 + r) * D_DIM + q * 8);
            *reinterpret_cast<uint4*>(sA + r * 136 + q * 8) = v;
        }
        __syncthreads();

        unsigned maddr = sbase + (unsigned)((row_off * 136 + k_off) * 2);
        for (int m = 0; m < 16; m++) {
            float acc[2][4] = {};
            unsigned a[2][4];
            asm volatile("ldmatrix.sync.aligned.m8n8.x4.shared.b16 {%0,%1,%2,%3}, [%4];"
                         : "=r"(a[0][0]), "=r"(a[0][1]), "=r"(a[0][2]), "=r"(a[0][3])
                         : "r"(maddr));
#pragma unroll
            for (int ks = 0; ks < 8; ks++) {
                if (ks < 7) {
                    unsigned* an = a[(ks + 1) & 1];
                    asm volatile("ldmatrix.sync.aligned.m8n8.x4.shared.b16 {%0,%1,%2,%3}, [%4];"
                                 : "=r"(an[0]), "=r"(an[1]), "=r"(an[2]), "=r"(an[3])
                                 : "r"(maddr + (unsigned)((ks + 1) * 32)));
                }
                const unsigned* ac = a[ks & 1];
#pragma unroll
                for (int t = 0; t < 2; t++) {
                    asm("mma.sync.aligned.m16n8k16.row.col.f32.bf16.bf16.f32 "
                        "{%0,%1,%2,%3}, {%4,%5,%6,%7}, {%8,%9}, {%0,%1,%2,%3};"
                        : "+f"(acc[t][0]), "+f"(acc[t][1]), "+f"(acc[t][2]), "+f"(acc[t][3])
                        : "r"(ac[0]), "r"(ac[1]), "r"(ac[2]), "r"(ac[3]),
                          "r"(br[t][ks][0]), "r"(br[t][ks][1]));
                }
            }
            maddr += 16 * 272;
#pragma unroll
            for (int t = 0; t < 2; t++) {
                ns[t][0] += ex2f(acc[t][0] * K2F) + ex2f(acc[t][2] * K2F);
                ns[t][1] += ex2f(acc[t][1] * K2F) + ex2f(acc[t][3] * K2F);
            }
        }
    }
#pragma unroll
    for (int o = 4; o < 32; o <<= 1)
#pragma unroll
        for (int t = 0; t < 2; t++)
#pragma unroll
            for (int j = 0; j < 2; j++)
                ns[t][j] += __shfl_xor_sync(0xffffffffu, ns[t][j], o);

    if (g == 0) {
#pragma unroll
        for (int t = 0; t < 2; t++)
#pragma unroll
            for (int j = 0; j < 2; j++)
                atomicAdd(&g_Nbuf[cbase + t * 8 + tg * 2 + j], ns[t][j]);
    }

    // ---- grid barrier 1: all 392 blocks (Nbuf complete) ----
    __syncthreads();
    if (tid == 0) {
        __threadfence();
        atomicAdd(&g_ph1, 1);
        while (*(volatile int*)&g_ph1 < 392) { }
    }
    __syncthreads();
    __threadfence();
    if (blockIdx.x >= 256) return;               // extra blocks done

    // ---- phase 1: one-hot exp terms + stats -> cterm (2 rows per block) ---
    __shared__ float s1[2][4], s2[2][4], red[2][4];
    const int hb = tid >> 7, d = tid & 127;
    const int b = blockIdx.x * 2 + hb;
    const int c = T[b];

    const float* pr = proxies + (size_t)c * D_DIM;
    float p = pr[d];
    float v = wred(p * p);
    if ((d & 31) == 0) s1[hb][d >> 5] = v;
    __syncthreads();
    float ssq = s1[hb][0] + s1[hb][1] + s1[hb][2] + s1[hb][3];
    float inv = 1.0f / sqrtf(ssq + 1e-12f);
    float x = g_Xn[b * D_DIM + d];
    float v2 = wred(x * (p * inv));
    if ((d & 31) == 0) s2[hb][d >> 5] = v2;
    __syncthreads();
    if (d == 0) {
        float cosv = s2[hb][0] + s2[hb][1] + s2[hb][2] + s2[hb][3];
        atomicAdd(&g_Nbuf[c], -ex2f(K2F * cosv));
        atomicAdd(&g_Pbuf[c],  ex2f(-K2F * cosv));
    }

    bool rep = (g_first[c] == B_N - b);          // uniform per half-block
    float n   = (float)g_scnt[b];
    float s   = g_ssum[b * D_DIM + d];
    float s2v = g_ssq [b * D_DIM + d];
    float mean = s / n;
    float var  = s2v / n - mean * mean;
    var = fminf(fmaxf(var, 1e-6f), 10.0f);
    float vv = wred(var);
    if ((d & 31) == 0) red[hb][d >> 5] = vv;
    __syncthreads();
    if (rep && d == 0) {
        float vmean = (red[hb][0] + red[hb][1] + red[hb][2] + red[hb][3]) * (1.0f / 128.0f);
        float vw  = 1.0f / (1.0f + vmean);
        float adj = g_center_sim[c] * vw * 0.15f;
        g_cterm[c] = K2F * (MRGF + adj);
        atomicAdd(&g_num_valid, 1);
    }

    // ---- grid barrier 2: blocks 0..255 (cterm/Nbuf/Pbuf complete) ----
    __syncthreads();
    if (tid == 0) {
        __threadfence();
        atomicAdd(&g_ph2, 1);
        while (*(volatile int*)&g_ph2 < 256) { }
    }
    __syncthreads();
    __threadfence();

    // self-clean g_first for the next run (after all readers)
    if (d == 0) g_first[c] = 0;

    // ---- phase 2: scaled log1p sums + final combine ----
    int i = blockIdx.x * 256 + tid;              // covers 65536 >= C_CLASSES
    float nl = 0.f, pl = 0.f;
    if (i < C_CLASSES) {
        float ctm = g_cterm[i];
        nl = log1pf(fmaxf(ex2f(ctm) * g_Nbuf[i], 0.f));
        pl = log1pf(ex2f(2.0f * K2F * MRGF - ctm) * g_Pbuf[i]);
    }
    __shared__ float sn[8], sp2[8];
    float aa = wred(nl);
    float b2 = wred(pl);
    int w = tid >> 5, l = tid & 31;
    if (l == 0) { sn[w] = aa; sp2[w] = b2; }
    __syncthreads();
    if (tid == 0) {
        float tn = 0.f, tp = 0.f;
#pragma unroll
        for (int k = 0; k < 8; k++) { tn += sn[k]; tp += sp2[k]; }
        atomicAdd(&g_acc[1], tn);
        atomicAdd(&g_acc[0], tp);
        __threadfence();
        int prev = atomicAdd(&g_done, 1);
        if (prev == 255) {
            volatile float* ac = g_acc;
            float pos = ac[0] / (float)g_num_valid;
            float neg = ac[1] * (1.0f / 50000.0f);
            float reg = ac[2] * (1.0f / (50000.0f * 128.0f));
            out[0] = pos + neg + 0.01f * reg;
        }
    }
}

// ---------------- launch: 3 kernels ----------------------------------------
extern "C" void kernel_launch(void* const* d_in, const int* in_sizes, int n_in,
                              void* d_out, int out_size) {
    const float* X       = (const float*)d_in[0];
    const int*   T       = (const int*)d_in[1];
    const float* proxies = (const float*)d_in[2];
    const float* centers = (const float*)d_in[3];
    float* out = (float*)d_out;

    const int gemm_smem = 256 * 136 * 2;   // 69632 B dynamic smem
    cudaFuncSetAttribute(k_gemmfinal, cudaFuncAttributeMaxDynamicSharedMemorySize,
                         gemm_smem);

    k_xnz      <<<512, 128>>>(X, T);
    k_pnorm    <<<C_PAD / 32, 256>>>(proxies, centers, T);
    k_gemmfinal<<<392, 256, gemm_smem>>>(T, proxies, out);
}